// round 12
// baseline (speedup 1.0000x reference)
#include <cuda_runtime.h>
#include <cuda_fp16.h>

#define BB 2
#define LL 16
#define CC 16
#define HH 64
#define WW 64
#define HW (HH*WW)

#define PW 68                 // padded width in 32B pixel-chunks; 68*32 = 2176 = 17*128
#define PH 66                 // padded height (rows -1..64)
#define PCH (PW*PH)
#define IMG_BYTES (PCH*32)    // 143616

// Zero-padded channel-last fp16 image cache. Chunk (y,x) (32B = 16 halves) at
// chunk index (y+1)*PW + (x+1), for x,y in [-1,64].
__device__ uint4 g_pad[BB*LL*PCH*2];

// ---------------------------------------------------------------------------
// Kernel 1: images (B,L,C,H,W) fp32 -> padded channel-last fp16 (zero border)
// ---------------------------------------------------------------------------
__global__ __launch_bounds__(256) void pad_kernel(const float* __restrict__ images) {
    int i = blockIdx.x * 256 + threadIdx.x;      // [0, BB*LL*PCH)
    int bl = i / PCH;
    int s  = i - bl * PCH;
    int y  = s / PW;
    int x  = s - y * PW;
    uint4 v0 = make_uint4(0u,0u,0u,0u), v1 = v0;
    if (x >= 1 && x <= WW && y >= 1 && y <= HH) {
        int px = (y - 1) * WW + (x - 1);
        const float* sp = images + (size_t)bl * CC * HW + px;
        unsigned u[8];
#pragma unroll
        for (int c = 0; c < 8; c++) {
            __half2 hh = __floats2half2_rn(sp[(2*c) * HW], sp[(2*c+1) * HW]);
            u[c] = *(unsigned*)&hh;
        }
        v0 = make_uint4(u[0], u[1], u[2], u[3]);
        v1 = make_uint4(u[4], u[5], u[6], u[7]);
    }
    uint4* d = g_pad + (size_t)i * 2;
    d[0] = v0;
    d[1] = v1;
}

// ---------------------------------------------------------------------------
// Kernel 2: main.
// Phase 0: fused cumsum of flows into smem (scum).
// Phase 1: each (pixel,k) task computed ONCE: {byte offset, weight pairs}
//          packed into a uint4 smem table (dedups the coord math that was
//          previously replicated across the 4 lanes of a pixel).
// Phase 2: gather loop per k: broadcast LDS.128 of the task + 2 LDG + 8 HFMA2.
//          LDG address depends only on the LDS -> loads issue immediately,
//          keeping the L1 queue full (this was the exposed-latency term).
// 4 lanes per pixel (q = (xq<<1)|cq) — wavefront-optimal gather mapping.
// ---------------------------------------------------------------------------
__global__ __launch_bounds__(256) void main_kernel(const float* __restrict__ flows,
                                                   float* __restrict__ out) {
    __shared__ float2 scum[LL * 64];   // 8 KB
    __shared__ uint4  stask[LL * 64];  // 16 KB: {off, wl(half2), wr(half2), 0}

    int bt  = blockIdx.x >> 6;        // 64 blocks per (b,t), 64 pixels each
    int blk = blockIdx.x & 63;        // pixel row (h == blk since W == 64)
    int t   = 15 - (bt >> 1);         // heavy t first across BOTH batches
    int b   = bt & 1;
    int p_base = blk * 64;
    int tid = threadIdx.x;

    // Phase 0: cumsum. threads 0..127 = 64 pixels x 2 components.
    if (tid < 128) {
        int comp = tid >> 6;
        int pl   = tid & 63;
        const float* fb = flows + ((size_t)b * LL * 2 + comp) * HW + p_base + pl;
        float c = 0.0f;
#pragma unroll
        for (int l = 0; l < LL; l++) {
            c += fb[l * 2 * HW];
            ((float*)&scum[l * 64 + pl])[comp] = c;
        }
    }
    __syncthreads();

    // Phase 1: one thread per (pixel,k) task (strided).
    {
        int ntask = (t + 1) << 6;
        for (int j = tid; j < ntask; j += 256) {
            int pl2 = j & 63;                 // j = k*64 + pl2; scum[j] == scum[k][pl2]
            float2 ck = scum[j];
            float2 cT = scum[(t << 6) + pl2];
            float cwx = fmaf(32.0f, cT.x, (float)pl2 + 0.5f);   // w = pl2
            float cwy = fmaf(32.0f, cT.y, (float)blk + 0.5f);   // h = blk
            float uxp = fmaf(-32.0f, ck.x, cwx);
            float uyp = fmaf(-32.0f, ck.y, cwy);
            // mod into [0,64): rxm == true rx + 0.5
            float rxm = fmaf(-floorf(uxp * 0.015625f), 64.0f, uxp);
            float rym = fmaf(-floorf(uyp * 0.015625f), 64.0f, uyp);
            float rx0 = rxm - 0.5f;
            float ry0 = rym - 0.5f;
            float fx0 = floorf(rx0);
            float fy0 = floorf(ry0);
            int x0 = (int)fx0;                // [-1, 63]
            int y0 = (int)fy0;
            float sx = rx0 - fx0;
            float sy = ry0 - fy0;
            float ax = 1.0f - sx;
            float ay = 1.0f - sy;
            __half2 wl = __floats2half2_rn(ax * ay, ax * sy);   // {top,bot} left col
            __half2 wr = __floats2half2_rn(sx * ay, sx * sy);   // {top,bot} right col
            stask[j] = make_uint4((unsigned)((y0 * PW + x0) * 32),
                                  *(unsigned*)&wl, *(unsigned*)&wr, 0u);
        }
    }
    __syncthreads();

    // Phase 2: gather.
    int pl = tid >> 2;
    int q  = tid & 3;
    int xq = q >> 1;                  // left/right column
    int cq = q & 1;                   // channel octet
    int p  = p_base + pl;

    __half2 zero = __float2half2_rn(0.0f);
    __half2 acc0 = zero, acc1 = zero, acc2 = zero, acc3 = zero;

    // base ptr: image series + (+1,+1) pad origin + lane column/octet offset
    const char* kb = (const char*)g_pad
                   + (size_t)(b * LL) * IMG_BYTES
                   + (size_t)((PW + 1 + xq) * 32 + cq * 16);

#pragma unroll 1
    for (int k = 0; k <= t; k++, kb += IMG_BYTES) {
        uint4 tk = stask[(k << 6) + pl];          // broadcast across 4 lanes
        int off = (int)tk.x;                      // may be negative (pad origin covers)
        unsigned wv = xq ? tk.z : tk.y;
        __half2 wvh = *(__half2*)&wv;
        __half2 wt2 = __half2half2(__low2half(wvh));
        __half2 wb2 = __half2half2(__high2half(wvh));

        const char* addr = kb + off;
        uint4 top = *(const uint4*)(addr);
        uint4 bot = *(const uint4*)(addr + PW * 32);

        const __half2* tp = (const __half2*)&top;
        const __half2* bp = (const __half2*)&bot;
        acc0 = __hfma2(tp[0], wt2, acc0);  acc0 = __hfma2(bp[0], wb2, acc0);
        acc1 = __hfma2(tp[1], wt2, acc1);  acc1 = __hfma2(bp[1], wb2, acc1);
        acc2 = __hfma2(tp[2], wt2, acc2);  acc2 = __hfma2(bp[2], wb2, acc2);
        acc3 = __hfma2(tp[3], wt2, acc3);  acc3 = __hfma2(bp[3], wb2, acc3);
    }

    // Merge left/right columns (partner lane q^2: same pixel, same octet)
    __half2 accv[4] = {acc0, acc1, acc2, acc3};
#pragma unroll
    for (int j = 0; j < 4; j++) {
        unsigned v = __shfl_xor_sync(0xffffffffu, *(unsigned*)&accv[j], 2);
        accv[j] = __hadd2(accv[j], *(__half2*)&v);
    }

    if (xq == 0) {
        // out layout (B,L,C,H,W); this lane owns channels [cq*8, cq*8+8)
        float* ob = out + ((size_t)(b * LL + t) * CC + cq * 8) * HW + p;
#pragma unroll
        for (int j = 0; j < 4; j++) {
            float2 f = __half22float2(accv[j]);
            ob[(2*j)     * HW] = f.x;
            ob[(2*j + 1) * HW] = f.y;
        }
    }
}

// ---------------------------------------------------------------------------
extern "C" void kernel_launch(void* const* d_in, const int* in_sizes, int n_in,
                              void* d_out, int out_size) {
    const float* flows  = (const float*)d_in[0];
    const float* images = (const float*)d_in[1];
    if (n_in >= 2 && in_sizes[0] > in_sizes[1]) {   // defensive: flows is smaller
        const float* tmp = flows; flows = images; images = tmp;
    }
    float* out = (float*)d_out;

    pad_kernel<<<(BB * LL * PCH + 255) / 256, 256>>>(images);
    main_kernel<<<BB * LL * 64, 256>>>(flows, out);
}

// round 14
// speedup vs baseline: 1.4250x; 1.4250x over previous
#include <cuda_runtime.h>
#include <cuda_fp16.h>

#define BB 2
#define LL 16
#define CC 16
#define HH 64
#define WW 64
#define HW (HH*WW)

#define PW 68                 // padded width in 32B pixel-chunks; 68*32 = 2176 = 17*128
#define PH 66                 // padded height (rows -1..64)
#define PCH (PW*PH)
#define IMG_BYTES (PCH*32)    // 143616

// Zero-padded channel-last fp16 image cache. Chunk (y,x) (32B = 16 halves) at
// chunk index (y+1)*PW + (x+1), for x,y in [-1,64].
__device__ uint4 g_pad[BB*LL*PCH*2];

// ---------------------------------------------------------------------------
// Kernel 1: images (B,L,C,H,W) fp32 -> padded channel-last fp16 (zero border)
// ---------------------------------------------------------------------------
__global__ __launch_bounds__(256) void pad_kernel(const float* __restrict__ images) {
    int i = blockIdx.x * 256 + threadIdx.x;      // [0, BB*LL*PCH)
    int bl = i / PCH;
    int s  = i - bl * PCH;
    int y  = s / PW;
    int x  = s - y * PW;
    uint4 v0 = make_uint4(0u,0u,0u,0u), v1 = v0;
    if (x >= 1 && x <= WW && y >= 1 && y <= HH) {
        int px = (y - 1) * WW + (x - 1);
        const float* sp = images + (size_t)bl * CC * HW + px;
        unsigned u[8];
#pragma unroll
        for (int c = 0; c < 8; c++) {
            __half2 hh = __floats2half2_rn(sp[(2*c) * HW], sp[(2*c+1) * HW]);
            u[c] = *(unsigned*)&hh;
        }
        v0 = make_uint4(u[0], u[1], u[2], u[3]);
        v1 = make_uint4(u[4], u[5], u[6], u[7]);
    }
    uint4* d = g_pad + (size_t)i * 2;
    d[0] = v0;
    d[1] = v1;
}

// ---------------------------------------------------------------------------
// Per-k coordinate/weight computation (one lane's view).
// ---------------------------------------------------------------------------
struct KW { int off; __half2 wt2, wb2; };

__device__ __forceinline__ KW kweights(float2 ck, float cwx, float cwy, int xq) {
    float uxp = fmaf(-32.0f, ck.x, cwx);
    float uyp = fmaf(-32.0f, ck.y, cwy);
    // mod into [0,64): rxm == true rx + 0.5
    float rxm = fmaf(-floorf(uxp * 0.015625f), 64.0f, uxp);
    float rym = fmaf(-floorf(uyp * 0.015625f), 64.0f, uyp);
    float rx0 = rxm - 0.5f;
    float ry0 = rym - 0.5f;
    float fx0 = floorf(rx0);
    float fy0 = floorf(ry0);
    int x0 = (int)fx0;        // [-1, 63]
    int y0 = (int)fy0;
    float sx = rx0 - fx0;
    float sy = ry0 - fy0;
    float xw = xq ? sx : (1.0f - sx);
    KW kw;
    kw.wt2 = __float2half2_rn(xw * (1.0f - sy));
    kw.wb2 = __float2half2_rn(xw * sy);
    kw.off = (y0 * PW + x0) * 32;
    return kw;
}

// ---------------------------------------------------------------------------
// Kernel 2: main. 4 lanes per pixel (q = (xq<<1)|cq) — wavefront-optimal.
// SOFTWARE PIPELINED: iteration k's (offset, weights) are computed in
// iteration k-1, so the two LDGs issue at the top of each iteration and
// their latency overlaps with the NEXT iteration's LDS+FFMA chain plus the
// current HFMA chain (loop-carried serial chain broken).
// ---------------------------------------------------------------------------
__global__ __launch_bounds__(256) void main_kernel(const float* __restrict__ flows,
                                                   float* __restrict__ out) {
    __shared__ float2 scum[LL * 64];

    int bt  = blockIdx.x >> 6;        // 64 blocks per (b,t), 64 pixels each
    int blk = blockIdx.x & 63;
    int t   = 15 - (bt >> 1);         // heavy t first, interleaved across b
    int b   = bt & 1;
    int p_base = blk * 64;
    int tid = threadIdx.x;

    // Fused cumsum: threads 0..127 = 64 pixels x 2 components.
    if (tid < 128) {
        int comp = tid >> 6;
        int pl   = tid & 63;
        const float* fb = flows + ((size_t)b * LL * 2 + comp) * HW + p_base + pl;
        float c = 0.0f;
#pragma unroll
        for (int l = 0; l < LL; l++) {
            c += fb[l * 2 * HW];
            ((float*)&scum[l * 64 + pl])[comp] = c;
        }
    }
    __syncthreads();

    int pl = tid >> 2;
    int q  = tid & 3;
    int xq = q >> 1;                  // left/right column
    int cq = q & 1;                   // channel octet
    int p  = p_base + pl;

    float2 ct = scum[t * 64 + pl];
    float cwx = fmaf(32.0f, ct.x, (float)(p & 63) + 0.5f);
    float cwy = fmaf(32.0f, ct.y, (float)(p >> 6) + 0.5f);

    __half2 zero = __float2half2_rn(0.0f);
    __half2 acc0 = zero, acc1 = zero, acc2 = zero, acc3 = zero;

    // base ptr: image series + (+1,+1) pad origin + lane column/octet offset
    const char* kb = (const char*)g_pad
                   + (size_t)(b * LL) * IMG_BYTES
                   + (size_t)((PW + 1 + xq) * 32 + cq * 16);

    // Prologue: compute k=0 state.
    KW cur = kweights(scum[pl], cwx, cwy, xq);

#pragma unroll 1
    for (int k = 0; k <= t; k++, kb += IMG_BYTES) {
        // Loads issue first, from state computed last iteration.
        const char* addr = kb + cur.off;
        uint4 top = *(const uint4*)(addr);
        uint4 bot = *(const uint4*)(addr + PW * 32);

        __half2 wt2 = cur.wt2;
        __half2 wb2 = cur.wb2;

        // Prefetch next iteration's state while the LDGs are in flight.
        int kn = min(k + 1, LL - 1);          // clamped: last-iter value unused
        cur = kweights(scum[kn * 64 + pl], cwx, cwy, xq);

        const __half2* tp = (const __half2*)&top;
        const __half2* bp = (const __half2*)&bot;
        acc0 = __hfma2(tp[0], wt2, acc0);  acc0 = __hfma2(bp[0], wb2, acc0);
        acc1 = __hfma2(tp[1], wt2, acc1);  acc1 = __hfma2(bp[1], wb2, acc1);
        acc2 = __hfma2(tp[2], wt2, acc2);  acc2 = __hfma2(bp[2], wb2, acc2);
        acc3 = __hfma2(tp[3], wt2, acc3);  acc3 = __hfma2(bp[3], wb2, acc3);
    }

    // Merge left/right columns (partner lane q^2: same pixel, same octet)
    __half2 accv[4] = {acc0, acc1, acc2, acc3};
#pragma unroll
    for (int j = 0; j < 4; j++) {
        unsigned v = __shfl_xor_sync(0xffffffffu, *(unsigned*)&accv[j], 2);
        accv[j] = __hadd2(accv[j], *(__half2*)&v);
    }

    if (xq == 0) {
        // out layout (B,L,C,H,W); this lane owns channels [cq*8, cq*8+8)
        float* ob = out + ((size_t)(b * LL + t) * CC + cq * 8) * HW + p;
#pragma unroll
        for (int j = 0; j < 4; j++) {
            float2 f = __half22float2(accv[j]);
            ob[(2*j)     * HW] = f.x;
            ob[(2*j + 1) * HW] = f.y;
        }
    }
}

// ---------------------------------------------------------------------------
extern "C" void kernel_launch(void* const* d_in, const int* in_sizes, int n_in,
                              void* d_out, int out_size) {
    const float* flows  = (const float*)d_in[0];
    const float* images = (const float*)d_in[1];
    if (n_in >= 2 && in_sizes[0] > in_sizes[1]) {   // defensive: flows is smaller
        const float* tmp = flows; flows = images; images = tmp;
    }
    float* out = (float*)d_out;

    pad_kernel<<<(BB * LL * PCH + 255) / 256, 256>>>(images);
    main_kernel<<<BB * LL * 64, 256>>>(flows, out);
}